// round 15
// baseline (speedup 1.0000x reference)
#include <cuda_runtime.h>
#include <float.h>

// features [4,256,50,50] f32 NCHW, rois [128,5] f32 (b,x1,y1,x2,y2),
// out [128,256,7,7] f32. Caffe geometry + reciprocal-multiply bin size
// (bin = roi * fl32(1/7)) — bit-exact vs gold since round 9.
//
// ROUND 15: ONE kernel. Block = (roi, 4-channel group). Phase 1 stages the
// ROI bounding rect for 4 channels into smem straight from NCHW (coalesced
// rows, each feature byte crosses L2 once). Phase 2: 196 threads compute the
// 49 bins x 4 channels from smem. No transpose, no edge table, no 2x
// window-overlap re-reads from L2.

#define NBINS 49
#define NROI  128
#define NCH   256
#define PLANE 2500   // 50*50

__global__ __launch_bounds__(256) void roi_pool_fused(
    const float* __restrict__ feat,
    const float* __restrict__ rois,
    float* __restrict__ out)
{
    __shared__ float s[4][PLANE];          // 40 KB; absolute (h,w) indexing

    const int n  = blockIdx.x >> 6;        // roi index (128)
    const int cg = blockIdx.x & 63;        // channel group (64 groups of 4)
    const int c0 = cg * 4;
    const int tid = threadIdx.x;

    // ---- ROI decode (uniform across block; bit-exact round-9 math) ----
    const float* r = rois + n * 5;
    const int   b  = (int)r[0];
    const float x1 = rintf(r[1] * 0.0625f);   // exact *2^-4, half-even
    const float y1 = rintf(r[2] * 0.0625f);
    const float x2 = rintf(r[3] * 0.0625f);
    const float y2 = rintf(r[4] * 0.0625f);

    const float roi_w = fmaxf(x2 - x1 + 1.0f, 1.0f);
    const float roi_h = fmaxf(y2 - y1 + 1.0f, 1.0f);

    const float C7 = 1.0f / 7.0f;             // fl32(1/7)
    const float bw = __fmul_rn(roi_w, C7);    // reciprocal-multiply div
    const float bh = __fmul_rn(roi_h, C7);

    // Bounding rect = union of all bin windows (edges monotone in pw/ph):
    //   [clip(x1), clip(ceil(7*bw)+x1))  x  [clip(y1), clip(ceil(7*bh)+y1))
    const int wr0 = (int)fminf(fmaxf(x1, 0.0f), 50.0f);
    const int wr1 = (int)fminf(fmaxf(ceilf(__fmul_rn(7.0f, bw)) + x1, 0.0f), 50.0f);
    const int hr0 = (int)fminf(fmaxf(y1, 0.0f), 50.0f);
    const int hr1 = (int)fminf(fmaxf(ceilf(__fmul_rn(7.0f, bh)) + y1, 0.0f), 50.0f);

    // ---- Phase 1: stage rect for 4 channels (64 lanes across w) ----
    {
        const int ch   = tid >> 6;            // 0..3
        const int lane = tid & 63;            // 0..63  (w offset; rect w <= 50)
        const int w    = wr0 + lane;
        if (w < wr1) {
            const float* __restrict__ base =
                feat + ((size_t)b * NCH + (c0 + ch)) * PLANE;
            for (int h = hr0; h < hr1; ++h) {
                s[ch][h * 50 + w] = __ldg(base + h * 50 + w);
            }
        }
    }
    __syncthreads();

    // ---- Phase 2: 49 bins x 4 channels from smem ----
    if (tid < NBINS * 4) {
        const int bin = tid % NBINS;          // bin fastest -> coalesced-ish out
        const int ch  = tid / NBINS;          // 0..3
        const int pw  = bin % 7;
        const int ph  = bin / 7;

        const float wstart = fminf(fmaxf(floorf(__fmul_rn((float)pw, bw))        + x1, 0.0f), 50.0f);
        const float wend   = fminf(fmaxf(ceilf (__fmul_rn((float)pw + 1.0f, bw)) + x1, 0.0f), 50.0f);
        const float hstart = fminf(fmaxf(floorf(__fmul_rn((float)ph, bh))        + y1, 0.0f), 50.0f);
        const float hend   = fminf(fmaxf(ceilf (__fmul_rn((float)ph + 1.0f, bh)) + y1, 0.0f), 50.0f);

        const int w0 = (int)wstart, w1 = (int)wend;
        const int h0 = (int)hstart, h1 = (int)hend;

        float m = -FLT_MAX;
        for (int h = h0; h < h1; ++h) {
            const float* rowp = &s[ch][h * 50];
            for (int w = w0; w < w1; ++w) {
                m = fmaxf(m, rowp[w]);
            }
        }

        const bool ne = (w1 > w0) && (h1 > h0);
        out[((size_t)n * NCH + c0 + ch) * NBINS + bin] = ne ? m : 0.0f;
    }
}

extern "C" void kernel_launch(void* const* d_in, const int* in_sizes, int n_in,
                              void* d_out, int out_size)
{
    const float* feat = nullptr;
    const float* rois = nullptr;
    for (int i = 0; i < n_in; ++i) {
        long s = in_sizes[i];
        if (s == 2560000L || s == 10240000L) feat = (const float*)d_in[i];
        else if (s == 640L || s == 2560L)    rois = (const float*)d_in[i];
    }
    if (!feat) feat = (const float*)d_in[0];
    if (!rois) rois = (const float*)d_in[n_in > 1 ? 1 : 0];

    roi_pool_fused<<<NROI * 64, 256>>>(feat, rois, (float*)d_out);  // 8192 blocks
}

// round 16
// speedup vs baseline: 1.4943x; 1.4943x over previous
#include <cuda_runtime.h>
#include <float.h>

// features [4,256,50,50] f32 NCHW, rois [128,5] f32, out [128,256,7,7] f32.
// Caffe geometry + reciprocal-multiply bin (roi * fl32(1/7)) — bit-exact gold.
//
// ROUND 16: round-14 architecture (transpose -> NHWC pool) with:
//  * pool threads = (n, bin, c2) float2 (802K threads): 2x warps in flight
//    to push the latency-limited L2 stream (was 48% L2, occ 54%).
//  * transpose with float4 smem-gather stores.

#define NBINS 49
#define NROI  128
#define NCH   256
#define PLANE 2500                         // 50*50
#define POOL_THREADS (NROI * NBINS * 128)  // 802,816

__device__ __align__(16) float g_tfeat[4 * PLANE * NCH];  // NHWC, 10.24 MB

// NCHW -> NHWC: g_tfeat[(b*2500+hw)*256 + c] = feat[(b*256+c)*2500 + hw]
__global__ void transpose_kernel(const float* __restrict__ feat)
{
    __shared__ float tile[32][33];         // tile[c_local][hw_local]
    const int b   = blockIdx.z;
    const int c0  = blockIdx.y * 32;
    const int hw0 = blockIdx.x * 32;
    const int tx  = threadIdx.x;           // 0..31
    const int ty  = threadIdx.y;           // 0..7
    const int t   = ty * 32 + tx;          // 0..255

    // Read: coalesced over hw
#pragma unroll
    for (int i = 0; i < 4; ++i) {
        const int c  = c0 + ty + i * 8;
        const int hw = hw0 + tx;
        if (hw < PLANE)
            tile[ty + i * 8][tx] = feat[((size_t)b * NCH + c) * PLANE + hw];
    }
    __syncthreads();

    // Write: each thread one float4 along c (256 threads x 4 floats = 1024)
    {
        const int hw_l = t >> 3;           // 0..31
        const int c4   = (t & 7) * 4;      // 0,4,...,28
        const int hw   = hw0 + hw_l;
        if (hw < PLANE) {
            float4 v;
            v.x = tile[c4 + 0][hw_l];
            v.y = tile[c4 + 1][hw_l];
            v.z = tile[c4 + 2][hw_l];
            v.w = tile[c4 + 3][hw_l];
            *reinterpret_cast<float4*>(
                &g_tfeat[((size_t)b * PLANE + hw) * NCH + c0 + c4]) = v;
        }
    }
}

__global__ void pool_kernel(const float* __restrict__ rois,
                            float* __restrict__ out)
{
    const int idx = blockIdx.x * blockDim.x + threadIdx.x;
    if (idx >= POOL_THREADS) return;

    const int c2  = idx & 127;       // fastest -> warp = 64 channels of one bin
    const int t   = idx >> 7;
    const int bin = t % NBINS;
    const int n   = t / NBINS;
    const int pw  = bin % 7;
    const int ph  = bin / 7;

    // ---- inline edge math (warp-uniform; bit-exact round-9 semantics) ----
    const float* r = rois + n * 5;
    const int   b  = (int)r[0];
    const float x1 = rintf(r[1] * 0.0625f);
    const float y1 = rintf(r[2] * 0.0625f);
    const float x2 = rintf(r[3] * 0.0625f);
    const float y2 = rintf(r[4] * 0.0625f);

    const float roi_w = fmaxf(x2 - x1 + 1.0f, 1.0f);
    const float roi_h = fmaxf(y2 - y1 + 1.0f, 1.0f);

    const float C7 = 1.0f / 7.0f;              // fl32(1/7)
    const float bw = __fmul_rn(roi_w, C7);     // reciprocal-multiply div
    const float bh = __fmul_rn(roi_h, C7);

    const float wstart = fminf(fmaxf(floorf(__fmul_rn((float)pw, bw))        + x1, 0.0f), 50.0f);
    const float wend   = fminf(fmaxf(ceilf (__fmul_rn((float)pw + 1.0f, bw)) + x1, 0.0f), 50.0f);
    const float hstart = fminf(fmaxf(floorf(__fmul_rn((float)ph, bh))        + y1, 0.0f), 50.0f);
    const float hend   = fminf(fmaxf(ceilf (__fmul_rn((float)ph + 1.0f, bh)) + y1, 0.0f), 50.0f);

    const int w0 = (int)wstart, w1 = (int)wend;
    const int h0 = (int)hstart, h1 = (int)hend;

    // ---- float2 window scan (256B coalesced per warp per cell) ----
    const float* __restrict__ base = g_tfeat + (size_t)b * PLANE * NCH + c2 * 2;

    float2 m = make_float2(-FLT_MAX, -FLT_MAX);
    for (int h = h0; h < h1; ++h) {
        const float* rp = base + (h * 50) * NCH;
        for (int w = w0; w < w1; ++w) {
            const float2 v = *reinterpret_cast<const float2*>(rp + w * NCH);
            m.x = fmaxf(m.x, v.x);
            m.y = fmaxf(m.y, v.y);
        }
    }

    const bool ne = (w1 > w0) && (h1 > h0);
    const int ob = (n * NCH + c2 * 2) * NBINS + bin;   // out [n, c, bin]
    out[ob]         = ne ? m.x : 0.0f;
    out[ob + NBINS] = ne ? m.y : 0.0f;
}

extern "C" void kernel_launch(void* const* d_in, const int* in_sizes, int n_in,
                              void* d_out, int out_size)
{
    const float* feat = nullptr;
    const float* rois = nullptr;
    for (int i = 0; i < n_in; ++i) {
        long s = in_sizes[i];
        if (s == 2560000L || s == 10240000L) feat = (const float*)d_in[i];
        else if (s == 640L || s == 2560L)    rois = (const float*)d_in[i];
    }
    if (!feat) feat = (const float*)d_in[0];
    if (!rois) rois = (const float*)d_in[n_in > 1 ? 1 : 0];

    dim3 tb(32, 8);
    dim3 tg((PLANE + 31) / 32, NCH / 32, 4);   // 79 x 8 x 4
    transpose_kernel<<<tg, tb>>>(feat);

    pool_kernel<<<(POOL_THREADS + 255) / 256, 256>>>(rois, (float*)d_out);
}

// round 17
// speedup vs baseline: 1.7554x; 1.1747x over previous
#include <cuda_runtime.h>
#include <float.h>

// features [4,256,50,50] f32 NCHW, rois [128,5] f32, out [128,256,7,7] f32.
// Caffe geometry + reciprocal-multiply bin (roi * fl32(1/7)) — bit-exact gold.
//
// ROUND 17: transpose -> NHWC; pool block = (roi, 32-channel group):
//  * all 49 bins of one (n,32ch) in one block -> L1 catches the ~1.8x
//    bin-window overlap (L2 traffic 77MB -> ~44MB)
//  * outputs staged in smem, written as 1568 contiguous floats
//    (kills the 32-sector-per-STG scatter that cost ~5us of L1 store pipe)

#define NBINS 49
#define NROI  128
#define NCH   256
#define PLANE 2500                 // 50*50
#define PTHREADS 448               // 14 warps: (bin 0..55 guarded, c4 0..7)

__device__ __align__(16) float g_tfeat[4 * PLANE * NCH];  // NHWC, 10.24 MB

// NCHW -> NHWC: g_tfeat[(b*2500+hw)*256 + c] = feat[(b*256+c)*2500 + hw]
__global__ void transpose_kernel(const float* __restrict__ feat)
{
    __shared__ float tile[32][33];
    const int b   = blockIdx.z;
    const int c0  = blockIdx.y * 32;
    const int hw0 = blockIdx.x * 32;
    const int tx  = threadIdx.x;
    const int ty  = threadIdx.y;
    const int t   = ty * 32 + tx;

#pragma unroll
    for (int i = 0; i < 4; ++i) {
        const int c  = c0 + ty + i * 8;
        const int hw = hw0 + tx;
        if (hw < PLANE)
            tile[ty + i * 8][tx] = feat[((size_t)b * NCH + c) * PLANE + hw];
    }
    __syncthreads();
    {
        const int hw_l = t >> 3;
        const int c4   = (t & 7) * 4;
        const int hw   = hw0 + hw_l;
        if (hw < PLANE) {
            float4 v;
            v.x = tile[c4 + 0][hw_l];
            v.y = tile[c4 + 1][hw_l];
            v.z = tile[c4 + 2][hw_l];
            v.w = tile[c4 + 3][hw_l];
            *reinterpret_cast<float4*>(
                &g_tfeat[((size_t)b * PLANE + hw) * NCH + c0 + c4]) = v;
        }
    }
}

__global__ __launch_bounds__(PTHREADS) void pool_kernel(
    const float* __restrict__ rois,
    float* __restrict__ out)
{
    __shared__ float s[NBINS * 33];        // s[bin*33 + ch], padded: no conflicts

    const int n  = blockIdx.x >> 3;        // roi (128)
    const int cq = blockIdx.x & 7;         // 32-channel group (8)
    const int tid = threadIdx.x;
    const int c4  = tid & 7;               // 0..7 -> channels c4*4..c4*4+3
    const int bin = tid >> 3;              // 0..55 (guard < 49)

    // ---- ROI decode (uniform per block; bit-exact round-9 math) ----
    const float* r = rois + n * 5;
    const int   b  = (int)r[0];
    const float x1 = rintf(r[1] * 0.0625f);
    const float y1 = rintf(r[2] * 0.0625f);
    const float x2 = rintf(r[3] * 0.0625f);
    const float y2 = rintf(r[4] * 0.0625f);

    const float roi_w = fmaxf(x2 - x1 + 1.0f, 1.0f);
    const float roi_h = fmaxf(y2 - y1 + 1.0f, 1.0f);

    const float C7 = 1.0f / 7.0f;              // fl32(1/7)
    const float bw = __fmul_rn(roi_w, C7);     // reciprocal-multiply div
    const float bh = __fmul_rn(roi_h, C7);

    if (bin < NBINS) {
        const int pw = bin % 7;
        const int ph = bin / 7;

        const float wstart = fminf(fmaxf(floorf(__fmul_rn((float)pw, bw))        + x1, 0.0f), 50.0f);
        const float wend   = fminf(fmaxf(ceilf (__fmul_rn((float)pw + 1.0f, bw)) + x1, 0.0f), 50.0f);
        const float hstart = fminf(fmaxf(floorf(__fmul_rn((float)ph, bh))        + y1, 0.0f), 50.0f);
        const float hend   = fminf(fmaxf(ceilf (__fmul_rn((float)ph + 1.0f, bh)) + y1, 0.0f), 50.0f);

        const int w0 = (int)wstart, w1 = (int)wend;
        const int h0 = (int)hstart, h1 = (int)hend;

        const float* __restrict__ base =
            g_tfeat + (size_t)b * PLANE * NCH + cq * 32 + c4 * 4;

        float4 m = make_float4(-FLT_MAX, -FLT_MAX, -FLT_MAX, -FLT_MAX);
        for (int h = h0; h < h1; ++h) {
            const float* rp = base + (h * 50) * NCH;
            for (int w = w0; w < w1; ++w) {
                const float4 v = *reinterpret_cast<const float4*>(rp + w * NCH);
                m.x = fmaxf(m.x, v.x);
                m.y = fmaxf(m.y, v.y);
                m.z = fmaxf(m.z, v.z);
                m.w = fmaxf(m.w, v.w);
            }
        }

        const bool ne = (w1 > w0) && (h1 > h0);
        const int sb = bin * 33 + c4 * 4;      // conflict-free (proof in notes)
        s[sb + 0] = ne ? m.x : 0.0f;
        s[sb + 1] = ne ? m.y : 0.0f;
        s[sb + 2] = ne ? m.z : 0.0f;
        s[sb + 3] = ne ? m.w : 0.0f;
    }
    __syncthreads();

    // ---- coalesced store: 1568 contiguous floats = out[n, cq*32..+32, :] ----
    const size_t obase = ((size_t)n * NCH + cq * 32) * NBINS;
#pragma unroll
    for (int i = 0; i < 4; ++i) {
        const int e = tid + i * PTHREADS;      // 0..1791, guard 1568
        if (e < 32 * NBINS) {
            const int ch = e / NBINS;
            const int bn = e % NBINS;
            out[obase + e] = s[bn * 33 + ch];
        }
    }
}

extern "C" void kernel_launch(void* const* d_in, const int* in_sizes, int n_in,
                              void* d_out, int out_size)
{
    const float* feat = nullptr;
    const float* rois = nullptr;
    for (int i = 0; i < n_in; ++i) {
        long s = in_sizes[i];
        if (s == 2560000L || s == 10240000L) feat = (const float*)d_in[i];
        else if (s == 640L || s == 2560L)    rois = (const float*)d_in[i];
    }
    if (!feat) feat = (const float*)d_in[0];
    if (!rois) rois = (const float*)d_in[n_in > 1 ? 1 : 0];

    dim3 tb(32, 8);
    dim3 tg((PLANE + 31) / 32, NCH / 32, 4);   // 79 x 8 x 4
    transpose_kernel<<<tg, tb>>>(feat);

    pool_kernel<<<NROI * 8, PTHREADS>>>(rois, (float*)d_out);  // 1024 blocks
}